// round 8
// baseline (speedup 1.0000x reference)
#include <cuda_runtime.h>
#include <cstdint>

// PoolingNms: MaxPool2d(k=3, stride=3) + MaxUnpool2d fused.
// x: [16, 1, 1536, 1536] fp32. Keep only the first-argmax element of each
// non-overlapping 3x3 block; zero elsewhere.
//
// R8: software-pipelined persistent CTAs. Tile = 3 full rows (18KB,
// contiguous in gmem). Each CTA owns 8 tiles; per iteration it commits the
// prefetched tile to smem, ISSUES THE NEXT TILE'S LOADS (which stay in
// flight through the entire compute phase), streams zeros over the current
// output tile, barriers once, then does the per-block argmax from smem and
// scatters only the maxima. Goal: remove the load/compute phase alternation
// that left DRAM at 64% in every previous structure.

static constexpr int W  = 1536;
static constexpr int H  = 1536;
static constexpr int BC = 16;
static constexpr int TROWS = 3;
static constexpr int TILE_FLOATS = TROWS * W;          // 4608 floats = 18KB
static constexpr int TILE_VEC8   = TILE_FLOATS / 8;    // 576
static constexpr int NTHREADS = 288;
static constexpr int V8T = TILE_VEC8 / NTHREADS;       // 2
static constexpr int NTILES = BC * H / TROWS;          // 8192
static constexpr int GRID = 1024;
static constexpr int TPC  = NTILES / GRID;             // 8 tiles per CTA
static constexpr int NPATCH = W / 12;                  // 128 patches per tile

__device__ __forceinline__ void ldg_v8_evict_last(const float* p, uint32_t r[8]) {
    asm("ld.global.L2::evict_last.v8.b32 {%0,%1,%2,%3,%4,%5,%6,%7}, [%8];"
        : "=r"(r[0]), "=r"(r[1]), "=r"(r[2]), "=r"(r[3]),
          "=r"(r[4]), "=r"(r[5]), "=r"(r[6]), "=r"(r[7])
        : "l"(p));
}

__device__ __forceinline__ void stg_v8_zero_evict_first(float* p) {
    asm volatile("st.global.L2::evict_first.v8.b32 [%0], {%1,%1,%1,%1,%1,%1,%1,%1};"
                 :: "l"(p), "r"(0u) : "memory");
}

__global__ __launch_bounds__(NTHREADS)
void pooling_nms_kernel(const float* __restrict__ x, float* __restrict__ out) {
    __shared__ __align__(32) float buf[2][TILE_FLOATS];

    const int tid = threadIdx.x;
    const size_t stride = (size_t)GRID * TILE_FLOATS;
    size_t base = (size_t)blockIdx.x * TILE_FLOATS;

    uint32_t pre[V8T][8];

    // Prologue: start loads for this CTA's first tile.
    #pragma unroll
    for (int j = 0; j < V8T; j++)
        ldg_v8_evict_last(x + base + (size_t)(tid + NTHREADS * j) * 8, pre[j]);

    int p = 0;
    for (int it = 0; it < TPC; it++) {
        const size_t cur = base;

        // Commit prefetched tile to smem buffer p.
        #pragma unroll
        for (int j = 0; j < V8T; j++) {
            uint4* sv = reinterpret_cast<uint4*>(
                buf[p] + (size_t)(tid + NTHREADS * j) * 8);
            sv[0] = make_uint4(pre[j][0], pre[j][1], pre[j][2], pre[j][3]);
            sv[1] = make_uint4(pre[j][4], pre[j][5], pre[j][6], pre[j][7]);
        }

        // Issue NEXT tile's loads — in flight during this tile's compute.
        if (it + 1 < TPC) {
            base += stride;
            #pragma unroll
            for (int j = 0; j < V8T; j++)
                ldg_v8_evict_last(x + base + (size_t)(tid + NTHREADS * j) * 8,
                                  pre[j]);
        }

        // Stream zeros over the current output tile.
        #pragma unroll
        for (int j = 0; j < V8T; j++)
            stg_v8_zero_evict_first(out + cur + (size_t)(tid + NTHREADS * j) * 8);

        __syncthreads();   // buf[p] ready; zeros ordered before scatters

        // Compute: 128 threads own one 3x12 patch (4 pool blocks) each.
        if (tid < NPATCH) {
            const float* rp = buf[p] + tid * 12;

            float best[4];
            int   ofs[4];                   // dr*W + col within patch

            #pragma unroll
            for (int dr = 0; dr < 3; dr++) {
                float4 a = *reinterpret_cast<const float4*>(rp + dr * W);
                float4 q = *reinterpret_cast<const float4*>(rp + dr * W + 4);
                float4 c = *reinterpret_cast<const float4*>(rp + dr * W + 8);
                float v[12] = {a.x, a.y, a.z, a.w, q.x, q.y, q.z, q.w,
                               c.x, c.y, c.z, c.w};
                #pragma unroll
                for (int col = 0; col < 12; col++) {
                    const int blk = col / 3;
                    const int o   = dr * W + col;
                    if (dr == 0 && (col % 3) == 0) {
                        best[blk] = v[col]; ofs[blk] = o;
                    } else if (v[col] > best[blk]) {  // strict >: first max wins
                        best[blk] = v[col]; ofs[blk] = o;
                    }
                }
            }

            // Scatter the 4 maxima (disjoint addresses; zeros already ordered).
            float* dp = out + cur + tid * 12;
            #pragma unroll
            for (int blk = 0; blk < 4; blk++)
                dp[ofs[blk]] = best[blk];
        }

        p ^= 1;
    }
}

extern "C" void kernel_launch(void* const* d_in, const int* in_sizes, int n_in,
                              void* d_out, int out_size) {
    const float* x = (const float*)d_in[0];
    float* out = (float*)d_out;
    pooling_nms_kernel<<<GRID, NTHREADS>>>(x, out);
}